// round 10
// baseline (speedup 1.0000x reference)
#include <cuda_runtime.h>
#include <cuda_fp16.h>
#include <float.h>
#include <cstdint>

#define NB   16
#define TT   4096
#define DD   64
#define KK   1024
#define SS   8
#define NV   (NB*TT)
#define TM   64
#define ZQ_ELEMS (NB*DD*TT)

// ---- device scratch ----
__device__ float        g_res[NV*DD];
__device__ float        g_q[NV*DD];
__device__ __half       g_resh16[NV*DD];
__device__ __half       g_resl16[NV*DD];
// fragment-packed codebook: [stage][blk(128)][kstep(4)][hl(2)][lane(32)][4 halves]
__device__ __half       g_cbfrag[SS*128*4*2*32*4];
__device__ float        g_hn[SS*KK];
__device__ float        g_loss[SS];
__device__ unsigned int g_cnt[SS*KK];

// ---- smem layout (bytes) ----
#define RSTR     144            // padded A row stride bytes (72 fp16)
#define TILE_A   (TM*RSTR)      // 9216
#define SM_HN    0
#define SM_FIN   4096
#define SM_RED   4608
#define SM_AH    8192
#define SM_AL    (SM_AH + TILE_A)
#define SM_TOTAL (SM_AL + TILE_A)   // 26624

// ---- PTX helpers ----
__device__ __forceinline__ void cpa16(uint32_t daddr, const void* src) {
    asm volatile("cp.async.cg.shared.global [%0], [%1], 16;" :: "r"(daddr), "l"(src) : "memory");
}
__device__ __forceinline__ void cpa_commit() { asm volatile("cp.async.commit_group;" ::: "memory"); }
__device__ __forceinline__ void cpa_wait0()  { asm volatile("cp.async.wait_group 0;" ::: "memory"); }

__device__ __forceinline__ void ldsm_x4(uint32_t* r, uint32_t a) {
    asm volatile("ldmatrix.sync.aligned.m8n8.x4.shared.b16 {%0,%1,%2,%3}, [%4];"
        : "=r"(r[0]), "=r"(r[1]), "=r"(r[2]), "=r"(r[3]) : "r"(a));
}
__device__ __forceinline__ void mma16816(float* c, const uint32_t* a, const uint2& b) {
    asm volatile("mma.sync.aligned.m16n8k16.row.col.f32.f16.f16.f32 "
        "{%0,%1,%2,%3}, {%4,%5,%6,%7}, {%8,%9}, {%0,%1,%2,%3};"
        : "+f"(c[0]), "+f"(c[1]), "+f"(c[2]), "+f"(c[3])
        : "r"(a[0]), "r"(a[1]), "r"(a[2]), "r"(a[3]), "r"(b.x), "r"(b.y));
}

// ---- transpose z [B,D,T] -> g_res [(b,t),d] + fp16 hi/lo; zero g_q ----
__global__ void transpose_in(const float* __restrict__ z) {
    __shared__ float tile[32][33];
    const int b  = blockIdx.z;
    const int t0 = blockIdx.x * 32;
    const int d0 = blockIdx.y * 32;
    #pragma unroll
    for (int j = 0; j < 32; j += 8)
        tile[threadIdx.y + j][threadIdx.x] = z[(b*DD + d0 + threadIdx.y + j)*TT + t0 + threadIdx.x];
    __syncthreads();
    #pragma unroll
    for (int j = 0; j < 32; j += 8) {
        int t = t0 + threadIdx.y + j;
        int d = d0 + threadIdx.x;
        int n = b*TT + t;
        float v = tile[threadIdx.x][threadIdx.y + j];
        g_res[n*DD + d] = v;
        g_q[n*DD + d]   = 0.0f;
        __half h = __float2half_rn(v);
        __half l = __float2half_rn(v - __half2float(h));
        g_resh16[n*DD + d] = h;
        g_resl16[n*DD + d] = l;
    }
}

__global__ void transpose_out(float* __restrict__ out) {
    __shared__ float tile[32][33];
    const int b  = blockIdx.z;
    const int t0 = blockIdx.x * 32;
    const int d0 = blockIdx.y * 32;
    #pragma unroll
    for (int j = 0; j < 32; j += 8)
        tile[threadIdx.y + j][threadIdx.x] = g_q[((size_t)b*TT + t0 + threadIdx.y + j)*DD + d0 + threadIdx.x];
    __syncthreads();
    #pragma unroll
    for (int j = 0; j < 32; j += 8)
        out[((size_t)b*DD + d0 + threadIdx.y + j)*TT + t0 + threadIdx.x] = tile[threadIdx.x][threadIdx.y + j];
}

// ---- codebook -> fragment-packed layout + halfnorms ----
__global__ void cb_split(const float* __restrict__ cbs) {
    int g = blockIdx.x * 128 + threadIdx.x;   // 0..8191 = s*1024 + j
    int s    = g >> 10;
    int j    = g & 1023;
    int blk  = j >> 3;
    int n_ib = j & 7;
    const float* src = cbs + (size_t)g * DD;
    __half* base = g_cbfrag + ((size_t)s*128*8) * 128;
    float s2 = 0.0f;
    #pragma unroll
    for (int k = 0; k < DD; k++) {
        float v = src[k];
        s2 += v*v;
        __half h = __float2half_rn(v);
        __half l = __float2half_rn(v - __half2float(h));
        int kstep = k >> 4, kk = k & 15;
        int reg  = kk >> 3;
        int lane = n_ib*4 + ((kk & 7) >> 1);
        int elem = kk & 1;
        size_t fh = ((size_t)(blk*8 + kstep*2 + 0)*32 + lane)*4 + reg*2 + elem;
        size_t fl = ((size_t)(blk*8 + kstep*2 + 1)*32 + lane)*4 + reg*2 + elem;
        base[fh] = h;
        base[fl] = l;
    }
    g_hn[g] = 0.5f * s2;
}

__global__ void zero_acc() {
    int i = blockIdx.x * 256 + threadIdx.x;
    if (i < SS*KK) g_cnt[i] = 0u;
    if (i < SS)    g_loss[i] = 0.0f;
}

// ---- main stage kernel: 128 threads (4 warps), 4 CTAs/SM;
//      all warps share the SAME B stream (L1-resident windows) ----
extern __shared__ char smem_raw[];

__global__ __launch_bounds__(128, 4)
void rvq_stage(const float* __restrict__ cb, int stage) {
    const int tid  = threadIdx.x;
    const int w    = tid >> 5;        // 0..3: rows w*16..+15
    const int lane = tid & 31;
    const int row0 = blockIdx.x * TM;
    uint32_t sb;
    asm("{ .reg .u64 t; cvta.to.shared.u64 t, %1; cvt.u32.u64 %0, t; }" : "=r"(sb) : "l"(smem_raw));

    float* hn_s = (float*)(smem_raw + SM_HN);
    int*   fin  = (int*)(smem_raw + SM_FIN);
    float* red  = (float*)(smem_raw + SM_RED);

    // ---- prologue: cp.async A(h,l) + hn, one barrier ----
    {
        const char* ah = (const char*)(g_resh16 + (size_t)row0*DD);
        const char* al = (const char*)(g_resl16 + (size_t)row0*DD);
        #pragma unroll
        for (int g = 0; g < 4; g++) {
            int idx = g*128 + tid;              // 512 granules per tile
            int r = idx >> 3, cc = idx & 7;
            uint32_t dof = r*RSTR + cc*16;
            int sof = r*128 + cc*16;
            cpa16(sb + SM_AH + dof, ah + sof);
            cpa16(sb + SM_AL + dof, al + sof);
        }
        #pragma unroll
        for (int g = 0; g < 2; g++)
            cpa16(sb + SM_HN + (g*128 + tid)*16, (const char*)(g_hn + stage*KK) + (g*128 + tid)*16);
        cpa_commit();
        cpa_wait0();
    }
    __syncthreads();

    uint32_t ahf[4][4], alf[4][4];
    const uint32_t a_addr = sb + SM_AH + (w*16 + (lane & 15))*RSTR + (lane >> 4)*16;
    #pragma unroll
    for (int s = 0; s < 4; s++) {
        ldsm_x4(ahf[s], a_addr + s*32);
        ldsm_x4(alf[s], a_addr + TILE_A + s*32);
    }

    // per-lane base into fragment-packed codebook (uint2 granularity)
    const uint2* bf = ((const uint2*)g_cbfrag) + (size_t)stage*32768 + lane;

    float bv0 = -FLT_MAX, bv1 = -FLT_MAX;
    int   bi0 = 0,        bi1 = 0;

    for (int cg = 0; cg < 16; cg++) {       // 16 chunks of 64 codes, shared by ALL warps
        const int blk0  = cg*8;
        const int cbase = blk0*8 + (lane & 3)*2;

        // init accumulators with -0.5||c||^2 (HMMA accumulates on top)
        float acc[8][4];
        #pragma unroll
        for (int nb = 0; nb < 8; nb++) {
            float h0 = -hn_s[cbase + nb*8];
            float h1 = -hn_s[cbase + nb*8 + 1];
            acc[nb][0] = h0; acc[nb][1] = h1; acc[nb][2] = h0; acc[nb][3] = h1;
        }

        // 2-stage register pipeline over (s, half): half = 4 blocks
        uint2 b0h[4], b0l[4], b1h[4], b1l[4];
        #pragma unroll
        for (int i = 0; i < 4; i++) {
            const uint2* p = bf + ((size_t)(blk0 + i)*8 + 0)*32;
            b0h[i] = __ldg(p);
            b0l[i] = __ldg(p + 32);
        }
        #pragma unroll
        for (int s = 0; s < 4; s++) {
            // prefetch half1 of this s
            #pragma unroll
            for (int i = 0; i < 4; i++) {
                const uint2* p = bf + ((size_t)(blk0 + 4 + i)*8 + s*2)*32;
                b1h[i] = __ldg(p);
                b1l[i] = __ldg(p + 32);
            }
            // compute half0 (12 MMAs)
            #pragma unroll
            for (int i = 0; i < 4; i++) mma16816(acc[i], ahf[s], b0h[i]);
            #pragma unroll
            for (int i = 0; i < 4; i++) mma16816(acc[i], alf[s], b0h[i]);
            #pragma unroll
            for (int i = 0; i < 4; i++) mma16816(acc[i], ahf[s], b0l[i]);
            // prefetch half0 of next s
            if (s < 3) {
                #pragma unroll
                for (int i = 0; i < 4; i++) {
                    const uint2* p = bf + ((size_t)(blk0 + i)*8 + (s+1)*2)*32;
                    b0h[i] = __ldg(p);
                    b0l[i] = __ldg(p + 32);
                }
            }
            // compute half1 (12 MMAs)
            #pragma unroll
            for (int i = 0; i < 4; i++) mma16816(acc[4+i], ahf[s], b1h[i]);
            #pragma unroll
            for (int i = 0; i < 4; i++) mma16816(acc[4+i], alf[s], b1h[i]);
            #pragma unroll
            for (int i = 0; i < 4; i++) mma16816(acc[4+i], ahf[s], b1l[i]);
        }

        // argmax fold: thread owns rows w*16 + lane/4 and +8
        #pragma unroll
        for (int nb = 0; nb < 8; nb++) {
            int col = cbase + nb*8;
            if (acc[nb][0] > bv0) { bv0 = acc[nb][0]; bi0 = col; }
            if (acc[nb][1] > bv0) { bv0 = acc[nb][1]; bi0 = col + 1; }
            if (acc[nb][2] > bv1) { bv1 = acc[nb][2]; bi1 = col; }
            if (acc[nb][3] > bv1) { bv1 = acc[nb][3]; bi1 = col + 1; }
        }
    }

    // ---- reduce over 4 lanes sharing a row (full code range already per thread) ----
    #pragma unroll
    for (int off = 1; off <= 2; off <<= 1) {
        float ov = __shfl_xor_sync(0xffffffffu, bv0, off);
        int   oi = __shfl_xor_sync(0xffffffffu, bi0, off);
        if (ov > bv0 || (ov == bv0 && oi < bi0)) { bv0 = ov; bi0 = oi; }
        ov = __shfl_xor_sync(0xffffffffu, bv1, off);
        oi = __shfl_xor_sync(0xffffffffu, bi1, off);
        if (ov > bv1 || (ov == bv1 && oi < bi1)) { bv1 = ov; bi1 = oi; }
    }
    if ((lane & 3) == 0) {
        int r0 = w*16 + (lane >> 2);
        fin[r0]     = bi0;
        fin[r0 + 8] = bi1;
        atomicAdd(&g_cnt[stage*KK + bi0], 1u);
        atomicAdd(&g_cnt[stage*KK + bi1], 1u);
    }
    __syncthreads();

    // ---- update: 2 threads per row, 32 d's each ----
    const int row  = tid >> 1;
    const int half = tid & 1;
    const int code = fin[row];
    const float4* qv   = (const float4*)(cb + (size_t)code*DD + half*32);
    float4*       rptr = (float4*)(g_res + (size_t)(row0+row)*DD + half*32);
    float4*       qptr = (float4*)(g_q   + (size_t)(row0+row)*DD + half*32);
    __half* th = g_resh16 + (size_t)(row0+row)*DD + half*32;
    __half* tl = g_resl16 + (size_t)(row0+row)*DD + half*32;
    float lsum = 0.0f;
    #pragma unroll
    for (int u = 0; u < 8; u++) {
        float4 q4 = qv[u];
        float4 r4 = rptr[u];
        float e0 = q4.x - r4.x, e1 = q4.y - r4.y, e2 = q4.z - r4.z, e3 = q4.w - r4.w;
        lsum += e0*e0 + e1*e1 + e2*e2 + e3*e3;
        float4 rn; rn.x = -e0; rn.y = -e1; rn.z = -e2; rn.w = -e3;
        rptr[u] = rn;
        float4 qa = qptr[u];
        qa.x += q4.x; qa.y += q4.y; qa.z += q4.z; qa.w += q4.w;
        qptr[u] = qa;
        float nv[4] = {rn.x, rn.y, rn.z, rn.w};
        #pragma unroll
        for (int e = 0; e < 4; e++) {
            __half h = __float2half_rn(nv[e]);
            __half l = __float2half_rn(nv[e] - __half2float(h));
            th[u*4 + e] = h;
            tl[u*4 + e] = l;
        }
    }

    __syncthreads();
    #pragma unroll
    for (int o = 16; o > 0; o >>= 1) lsum += __shfl_down_sync(0xffffffffu, lsum, o);
    if ((tid & 31) == 0) red[tid >> 5] = lsum;
    __syncthreads();
    if (tid == 0) {
        float tot = red[0] + red[1] + red[2] + red[3];
        atomicAdd(&g_loss[stage], tot);
    }
}

// ---- losses + perplexities ----
__global__ void finalize(float* __restrict__ out) {
    const int s = blockIdx.x;
    __shared__ float sh[256];
    float e = 0.0f;
    for (int k = threadIdx.x; k < KK; k += 256) {
        float p = (float)g_cnt[s*KK + k] / (float)NV;
        e += p * logf(p + 1e-10f);
    }
    sh[threadIdx.x] = e;
    __syncthreads();
    for (int o = 128; o > 0; o >>= 1) {
        if (threadIdx.x < o) sh[threadIdx.x] += sh[threadIdx.x + o];
        __syncthreads();
    }
    if (threadIdx.x == 0) {
        out[ZQ_ELEMS + s]      = g_loss[s] / (float)(NV*DD);
        out[ZQ_ELEMS + SS + s] = expf(-sh[0]);
    }
}

extern "C" void kernel_launch(void* const* d_in, const int* in_sizes, int n_in,
                              void* d_out, int out_size) {
    const float* z   = (const float*)d_in[0];
    const float* cbs = (const float*)d_in[1];
    float* out = (float*)d_out;

    static int inited = 0;
    if (!inited) {
        cudaFuncSetAttribute(rvq_stage, cudaFuncAttributeMaxDynamicSharedMemorySize, SM_TOTAL);
        inited = 1;
    }

    dim3 tb(32, 8);
    transpose_in<<<dim3(TT/32, DD/32, NB), tb>>>(z);
    zero_acc<<<32, 256>>>();
    cb_split<<<(SS*KK)/128, 128>>>(cbs);
    for (int s = 0; s < SS; s++) {
        rvq_stage<<<NV/TM, 128, SM_TOTAL>>>(cbs + (size_t)s*KK*DD, s);
    }
    finalize<<<SS, 256>>>(out);
    transpose_out<<<dim3(TT/32, DD/32, NB), tb>>>(out);
}

// round 11
// speedup vs baseline: 1.0328x; 1.0328x over previous
#include <cuda_runtime.h>
#include <cuda_fp16.h>
#include <float.h>
#include <cstdint>

#define NB   16
#define TT   4096
#define DD   64
#define KK   1024
#define SS   8
#define NV   (NB*TT)
#define TM   64
#define ZQ_ELEMS (NB*DD*TT)

// ---- device scratch ----
__device__ float        g_res[NV*DD];
__device__ float        g_q[NV*DD];
// fragment-packed codebook (hi only): [stage][blk(128)][kstep(4)][lane(32)][4 halves]
__device__ __half       g_cbfrag[SS*128*4*32*4];
__device__ float        g_hn[SS*KK];
__device__ float        g_loss[SS];
__device__ unsigned int g_cnt[SS*KK];

// ---- smem layout (bytes) ----
#define RSTR     144            // Ah row stride bytes (72 fp16)
#define RSTRF    68             // Af row stride floats
#define SM_HN    0              // 4096
#define SM_FIN   4096           // 256
#define SM_RED   4352           // 128
#define SM_TOP4  4480           // 64*4 ints = 1024
#define SM_M4V   5504           // 64*8*3 floats = 6144
#define SM_M4I   11648          // 64*8*3 ints  = 6144
#define SM_AF    17920          // 64*68*4 = 17408
#define SM_AH    35328          // 64*144  = 9216
#define SM_TOTAL 44544

// ---- PTX helpers ----
__device__ __forceinline__ void cpa16(uint32_t daddr, const void* src) {
    asm volatile("cp.async.cg.shared.global [%0], [%1], 16;" :: "r"(daddr), "l"(src) : "memory");
}
__device__ __forceinline__ void cpa_commit() { asm volatile("cp.async.commit_group;" ::: "memory"); }
__device__ __forceinline__ void cpa_wait0()  { asm volatile("cp.async.wait_group 0;" ::: "memory"); }

__device__ __forceinline__ void ldsm_x4(uint32_t* r, uint32_t a) {
    asm volatile("ldmatrix.sync.aligned.m8n8.x4.shared.b16 {%0,%1,%2,%3}, [%4];"
        : "=r"(r[0]), "=r"(r[1]), "=r"(r[2]), "=r"(r[3]) : "r"(a));
}
__device__ __forceinline__ void mma16816(float* c, const uint32_t* a, const uint2& b) {
    asm volatile("mma.sync.aligned.m16n8k16.row.col.f32.f16.f16.f32 "
        "{%0,%1,%2,%3}, {%4,%5,%6,%7}, {%8,%9}, {%0,%1,%2,%3};"
        : "+f"(c[0]), "+f"(c[1]), "+f"(c[2]), "+f"(c[3])
        : "r"(a[0]), "r"(a[1]), "r"(a[2]), "r"(a[3]), "r"(b.x), "r"(b.y));
}

__device__ __forceinline__ void ins3(float v, int i, float* tv, int* ti) {
    if (v > tv[2]) {
        if (v > tv[1]) {
            tv[2] = tv[1]; ti[2] = ti[1];
            if (v > tv[0]) { tv[1] = tv[0]; ti[1] = ti[0]; tv[0] = v; ti[0] = i; }
            else           { tv[1] = v;     ti[1] = i; }
        } else { tv[2] = v; ti[2] = i; }
    }
}

// ---- transpose z [B,D,T] -> g_res [(b,t),d]; zero g_q ----
__global__ void transpose_in(const float* __restrict__ z) {
    __shared__ float tile[32][33];
    const int b  = blockIdx.z;
    const int t0 = blockIdx.x * 32;
    const int d0 = blockIdx.y * 32;
    #pragma unroll
    for (int j = 0; j < 32; j += 8)
        tile[threadIdx.y + j][threadIdx.x] = z[(b*DD + d0 + threadIdx.y + j)*TT + t0 + threadIdx.x];
    __syncthreads();
    #pragma unroll
    for (int j = 0; j < 32; j += 8) {
        int t = t0 + threadIdx.y + j;
        int d = d0 + threadIdx.x;
        int n = b*TT + t;
        float v = tile[threadIdx.x][threadIdx.y + j];
        g_res[n*DD + d] = v;
        g_q[n*DD + d]   = 0.0f;
    }
}

__global__ void transpose_out(float* __restrict__ out) {
    __shared__ float tile[32][33];
    const int b  = blockIdx.z;
    const int t0 = blockIdx.x * 32;
    const int d0 = blockIdx.y * 32;
    #pragma unroll
    for (int j = 0; j < 32; j += 8)
        tile[threadIdx.y + j][threadIdx.x] = g_q[((size_t)b*TT + t0 + threadIdx.y + j)*DD + d0 + threadIdx.x];
    __syncthreads();
    #pragma unroll
    for (int j = 0; j < 32; j += 8)
        out[((size_t)b*DD + d0 + threadIdx.y + j)*TT + t0 + threadIdx.x] = tile[threadIdx.x][threadIdx.y + j];
}

// ---- codebook -> fragment-packed (hi only) + halfnorms ----
__global__ void cb_split(const float* __restrict__ cbs) {
    int g = blockIdx.x * 128 + threadIdx.x;   // 0..8191 = s*1024 + j
    int s    = g >> 10;
    int j    = g & 1023;
    int blk  = j >> 3;
    int n_ib = j & 7;
    const float* src = cbs + (size_t)g * DD;
    __half* base = g_cbfrag + (size_t)s * (128*4*32*4);
    float s2 = 0.0f;
    #pragma unroll
    for (int k = 0; k < DD; k++) {
        float v = src[k];
        s2 += v*v;
        __half h = __float2half_rn(v);
        int kstep = k >> 4, kk = k & 15;
        int reg  = kk >> 3;
        int lane = n_ib*4 + ((kk & 7) >> 1);
        int elem = kk & 1;
        base[((size_t)(blk*4 + kstep)*32 + lane)*4 + reg*2 + elem] = h;
    }
    g_hn[g] = 0.5f * s2;
}

__global__ void zero_acc() {
    int i = blockIdx.x * 256 + threadIdx.x;
    if (i < SS*KK) g_cnt[i] = 0u;
    if (i < SS)    g_loss[i] = 0.0f;
}

// ---- main stage kernel: coarse 1-term fp16 MMA + top-4 exact fp32 rescore ----
extern __shared__ char smem_raw[];

__global__ __launch_bounds__(256, 2)
void rvq_stage(const float* __restrict__ cb, int stage) {
    const int tid  = threadIdx.x;
    const int w    = tid >> 5;
    const int lane = tid & 31;
    const int wrow = w >> 1;          // 0..3: rows wrow*16..+15
    const int wcol = w & 1;           // 0..1: blocks wcol*64..+63
    const int row0 = blockIdx.x * TM;
    uint32_t sb;
    asm("{ .reg .u64 t; cvta.to.shared.u64 t, %1; cvt.u32.u64 %0, t; }" : "=r"(sb) : "l"(smem_raw));

    float* hn_s = (float*)(smem_raw + SM_HN);
    int*   fin  = (int*)(smem_raw + SM_FIN);
    float* red  = (float*)(smem_raw + SM_RED);
    int*   top4 = (int*)(smem_raw + SM_TOP4);
    float* m4v  = (float*)(smem_raw + SM_M4V);
    int*   m4i  = (int*)(smem_raw + SM_M4I);
    float* Af   = (float*)(smem_raw + SM_AF);

    // ---- prologue: cp.async fp32 residual tile + hn ----
    {
        const char* af = (const char*)(g_res + (size_t)row0*DD);
        #pragma unroll
        for (int g = 0; g < 4; g++) {
            int idx = g*256 + tid;              // 1024 granules (16B), 64 rows x 16
            int r = idx >> 4, c = idx & 15;
            cpa16(sb + SM_AF + r*(RSTRF*4) + c*16, af + r*256 + c*16);
        }
        cpa16(sb + SM_HN + tid*16, (const char*)(g_hn + stage*KK) + tid*16);
        cpa_commit();
        cpa_wait0();
    }
    __syncthreads();

    // build Ah (fp16) from Af: each thread converts a quarter row
    {
        int r  = tid >> 2;
        int k0 = (tid & 3) * 16;
        const float* src = Af + r*RSTRF + k0;
        __half2* dst = (__half2*)(smem_raw + SM_AH + r*RSTR + k0*2);
        #pragma unroll
        for (int j = 0; j < 8; j++)
            dst[j] = __floats2half2_rn(src[j*2], src[j*2+1]);
    }
    __syncthreads();

    uint32_t ahf[4][4];
    const uint32_t a_addr = sb + SM_AH + (wrow*16 + (lane & 15))*RSTR + (lane >> 4)*16;
    #pragma unroll
    for (int s = 0; s < 4; s++) ldsm_x4(ahf[s], a_addr + s*32);

    // per-lane base into fragment-packed codebook (uint2 granularity)
    const uint2* bf = ((const uint2*)g_cbfrag) + (size_t)stage*16384 + lane;

    // per-thread top-3 for each of the thread's two rows
    float tv0[3] = {-FLT_MAX, -FLT_MAX, -FLT_MAX};
    float tv1[3] = {-FLT_MAX, -FLT_MAX, -FLT_MAX};
    int   ti0[3] = {0x7fffffff, 0x7fffffff, 0x7fffffff};
    int   ti1[3] = {0x7fffffff, 0x7fffffff, 0x7fffffff};

    for (int cg = 0; cg < 8; cg++) {
        const int blk0  = wcol*64 + cg*8;
        const int cbase = blk0*8 + (lane & 3)*2;

        float acc[8][4];
        #pragma unroll
        for (int nb = 0; nb < 8; nb++) {
            float h0 = -hn_s[cbase + nb*8];
            float h1 = -hn_s[cbase + nb*8 + 1];
            acc[nb][0] = h0; acc[nb][1] = h1; acc[nb][2] = h0; acc[nb][3] = h1;
        }

        // 2-stage register pipeline, half = 4 blocks (hi term only)
        uint2 b0[4], b1[4];
        #pragma unroll
        for (int i = 0; i < 4; i++)
            b0[i] = __ldg(bf + ((size_t)(blk0 + i)*4 + 0)*32);
        #pragma unroll
        for (int s = 0; s < 4; s++) {
            #pragma unroll
            for (int i = 0; i < 4; i++)
                b1[i] = __ldg(bf + ((size_t)(blk0 + 4 + i)*4 + s)*32);
            #pragma unroll
            for (int i = 0; i < 4; i++) mma16816(acc[i], ahf[s], b0[i]);
            if (s < 3) {
                #pragma unroll
                for (int i = 0; i < 4; i++)
                    b0[i] = __ldg(bf + ((size_t)(blk0 + i)*4 + s + 1)*32);
            }
            #pragma unroll
            for (int i = 0; i < 4; i++) mma16816(acc[4+i], ahf[s], b1[i]);
        }

        // top-3 fold
        #pragma unroll
        for (int nb = 0; nb < 8; nb++) {
            int col = cbase + nb*8;
            ins3(acc[nb][0], col,     tv0, ti0);
            ins3(acc[nb][1], col + 1, tv0, ti0);
            ins3(acc[nb][2], col,     tv1, ti1);
            ins3(acc[nb][3], col + 1, tv1, ti1);
        }
    }

    // ---- write per-thread top-3 to smem: 8 slots per row ----
    {
        int r0   = wrow*16 + (lane >> 2);
        int slot = wcol*4 + (lane & 3);
        #pragma unroll
        for (int t = 0; t < 3; t++) {
            m4v[(r0*8 + slot)*3 + t]       = tv0[t];
            m4i[(r0*8 + slot)*3 + t]       = ti0[t];
            m4v[((r0+8)*8 + slot)*3 + t]   = tv1[t];
            m4i[((r0+8)*8 + slot)*3 + t]   = ti1[t];
        }
    }
    __syncthreads();

    // ---- merge: one thread per row keeps top-4 of 24 candidates ----
    if (tid < TM) {
        float mv[4] = {-FLT_MAX, -FLT_MAX, -FLT_MAX, -FLT_MAX};
        int   mi[4] = {0x7fffffff, 0x7fffffff, 0x7fffffff, 0x7fffffff};
        #pragma unroll 4
        for (int e = 0; e < 24; e++) {
            float v = m4v[tid*24 + e];
            int   i = m4i[tid*24 + e];
            if (v > mv[3] || (v == mv[3] && i < mi[3])) {
                int k = 3;
                while (k > 0 && (v > mv[k-1] || (v == mv[k-1] && i < mi[k-1]))) {
                    mv[k] = mv[k-1]; mi[k] = mi[k-1]; k--;
                }
                mv[k] = v; mi[k] = i;
            }
        }
        #pragma unroll
        for (int k = 0; k < 4; k++) top4[tid*4 + k] = mi[k];
    }
    __syncthreads();

    // ---- exact fp32 rescore: 4 threads per row ----
    {
        int row = tid >> 2;
        int c   = tid & 3;
        int idx = top4[row*4 + c];
        const float4* cp = (const float4*)(cb + (size_t)idx*DD);
        const float*  af = Af + row*RSTRF;
        float s0 = 0.f, s1 = 0.f, s2 = 0.f, s3 = 0.f;
        #pragma unroll
        for (int u = 0; u < 16; u++) {
            float4 q = __ldg(cp + u);
            s0 += q.x * af[u*4];
            s1 += q.y * af[u*4+1];
            s2 += q.z * af[u*4+2];
            s3 += q.w * af[u*4+3];
        }
        float sc = (s0 + s1) + (s2 + s3) - hn_s[idx];
        #pragma unroll
        for (int off = 1; off <= 2; off <<= 1) {
            float ov = __shfl_xor_sync(0xffffffffu, sc, off);
            int   oi = __shfl_xor_sync(0xffffffffu, idx, off);
            if (ov > sc || (ov == sc && oi < idx)) { sc = ov; idx = oi; }
        }
        if (c == 0) {
            fin[row] = idx;
            atomicAdd(&g_cnt[stage*KK + idx], 1u);
        }
    }
    __syncthreads();

    // ---- update: 4 threads per row, 16 d's each (residual from smem Af) ----
    const int row = tid >> 2;
    const int qt  = tid & 3;
    const int code = fin[row];
    const float4* qv   = (const float4*)(cb + (size_t)code*DD + qt*16);
    float4*       rptr = (float4*)(g_res + (size_t)(row0+row)*DD + qt*16);
    float4*       qptr = (float4*)(g_q   + (size_t)(row0+row)*DD + qt*16);
    const float*  af   = Af + row*RSTRF + qt*16;
    float lsum = 0.0f;
    #pragma unroll
    for (int u = 0; u < 4; u++) {
        float4 q4 = qv[u];
        float r0 = af[u*4], r1 = af[u*4+1], r2 = af[u*4+2], r3 = af[u*4+3];
        float e0 = q4.x - r0, e1 = q4.y - r1, e2 = q4.z - r2, e3 = q4.w - r3;
        lsum += e0*e0 + e1*e1 + e2*e2 + e3*e3;
        float4 rn; rn.x = -e0; rn.y = -e1; rn.z = -e2; rn.w = -e3;
        rptr[u] = rn;
        float4 qa = qptr[u];
        qa.x += q4.x; qa.y += q4.y; qa.z += q4.z; qa.w += q4.w;
        qptr[u] = qa;
    }

    __syncthreads();
    #pragma unroll
    for (int o = 16; o > 0; o >>= 1) lsum += __shfl_down_sync(0xffffffffu, lsum, o);
    if ((tid & 31) == 0) red[tid >> 5] = lsum;
    __syncthreads();
    if (tid == 0) {
        float tot = 0.0f;
        #pragma unroll
        for (int ww = 0; ww < 8; ww++) tot += red[ww];
        atomicAdd(&g_loss[stage], tot);
    }
}

// ---- losses + perplexities ----
__global__ void finalize(float* __restrict__ out) {
    const int s = blockIdx.x;
    __shared__ float sh[256];
    float e = 0.0f;
    for (int k = threadIdx.x; k < KK; k += 256) {
        float p = (float)g_cnt[s*KK + k] / (float)NV;
        e += p * logf(p + 1e-10f);
    }
    sh[threadIdx.x] = e;
    __syncthreads();
    for (int o = 128; o > 0; o >>= 1) {
        if (threadIdx.x < o) sh[threadIdx.x] += sh[threadIdx.x + o];
        __syncthreads();
    }
    if (threadIdx.x == 0) {
        out[ZQ_ELEMS + s]      = g_loss[s] / (float)(NV*DD);
        out[ZQ_ELEMS + SS + s] = expf(-sh[0]);
    }
}

extern "C" void kernel_launch(void* const* d_in, const int* in_sizes, int n_in,
                              void* d_out, int out_size) {
    const float* z   = (const float*)d_in[0];
    const float* cbs = (const float*)d_in[1];
    float* out = (float*)d_out;

    static int inited = 0;
    if (!inited) {
        cudaFuncSetAttribute(rvq_stage, cudaFuncAttributeMaxDynamicSharedMemorySize, SM_TOTAL);
        inited = 1;
    }

    dim3 tb(32, 8);
    transpose_in<<<dim3(TT/32, DD/32, NB), tb>>>(z);
    zero_acc<<<32, 256>>>();
    cb_split<<<(SS*KK)/128, 128>>>(cbs);
    for (int s = 0; s < SS; s++) {
        rvq_stage<<<NV/TM, 256, SM_TOTAL>>>(cbs + (size_t)s*KK*DD, s);
    }
    finalize<<<SS, 256>>>(out);
    transpose_out<<<dim3(TT/32, DD/32, NB), tb>>>(out);
}

// round 12
// speedup vs baseline: 1.5382x; 1.4893x over previous
#include <cuda_runtime.h>
#include <cuda_fp16.h>
#include <float.h>
#include <cstdint>

#define NB   16
#define TT   4096
#define DD   64
#define KK   1024
#define SS   8
#define NV   (NB*TT)
#define TM   64
#define ZQ_ELEMS (NB*DD*TT)

// ---- device scratch ----
__device__ float        g_res[NV*DD];     // initial residual (written once by transpose_in)
__device__ float        g_q[NV*DD];
// fragment-packed codebook (hi, uint4-kpair): [stage][blk(128)][kpair(2)][lane(32)][8 halves]
__device__ __half       g_cbfrag[SS*128*2*32*8];
__device__ float        g_hn[SS*KK];
__device__ float        g_loss[SS];
__device__ unsigned int g_cnt[SS*KK];

// ---- smem layout (bytes) ----
#define RSTR     144            // Ah row stride bytes (72 fp16)
#define RSTRF    68             // Af row stride floats (272B)
#define SM_HN    0              // 8*1024*4 = 32768
#define SM_FIN   32768          // 256
#define SM_RED   33024          // 128
#define SM_TOP4  33152          // 64*4*4 = 1024
#define SM_M4V   34176          // 64*16*4 = 4096
#define SM_M4I   38272          // 4096
#define SM_AF    42368          // 64*272 = 17408
#define SM_AH    59776          // 64*144 = 9216
#define SM_TOTAL 68992

// ---- PTX helpers ----
__device__ __forceinline__ void cpa16(uint32_t daddr, const void* src) {
    asm volatile("cp.async.cg.shared.global [%0], [%1], 16;" :: "r"(daddr), "l"(src) : "memory");
}
__device__ __forceinline__ void cpa_commit() { asm volatile("cp.async.commit_group;" ::: "memory"); }
__device__ __forceinline__ void cpa_wait0()  { asm volatile("cp.async.wait_group 0;" ::: "memory"); }

__device__ __forceinline__ void ldsm_x4(uint32_t* r, uint32_t a) {
    asm volatile("ldmatrix.sync.aligned.m8n8.x4.shared.b16 {%0,%1,%2,%3}, [%4];"
        : "=r"(r[0]), "=r"(r[1]), "=r"(r[2]), "=r"(r[3]) : "r"(a));
}
__device__ __forceinline__ void mma16816(float* c, const uint32_t* a, uint32_t b0, uint32_t b1) {
    asm volatile("mma.sync.aligned.m16n8k16.row.col.f32.f16.f16.f32 "
        "{%0,%1,%2,%3}, {%4,%5,%6,%7}, {%8,%9}, {%0,%1,%2,%3};"
        : "+f"(c[0]), "+f"(c[1]), "+f"(c[2]), "+f"(c[3])
        : "r"(a[0]), "r"(a[1]), "r"(a[2]), "r"(a[3]), "r"(b0), "r"(b1));
}

__device__ __forceinline__ void ins2(float v, int i, float& v0, int& i0, float& v1, int& i1) {
    if (v > v1) {
        if (v > v0) { v1 = v0; i1 = i0; v0 = v; i0 = i; }
        else        { v1 = v;  i1 = i; }
    }
}

// ---- transpose z [B,D,T] -> g_res [(b,t),d] ----
__global__ void transpose_in(const float* __restrict__ z) {
    __shared__ float tile[32][33];
    const int b  = blockIdx.z;
    const int t0 = blockIdx.x * 32;
    const int d0 = blockIdx.y * 32;
    #pragma unroll
    for (int j = 0; j < 32; j += 8)
        tile[threadIdx.y + j][threadIdx.x] = z[(b*DD + d0 + threadIdx.y + j)*TT + t0 + threadIdx.x];
    __syncthreads();
    #pragma unroll
    for (int j = 0; j < 32; j += 8) {
        int t = t0 + threadIdx.y + j;
        int d = d0 + threadIdx.x;
        g_res[(b*TT + t)*DD + d] = tile[threadIdx.x][threadIdx.y + j];
    }
}

__global__ void transpose_out(float* __restrict__ out) {
    __shared__ float tile[32][33];
    const int b  = blockIdx.z;
    const int t0 = blockIdx.x * 32;
    const int d0 = blockIdx.y * 32;
    #pragma unroll
    for (int j = 0; j < 32; j += 8)
        tile[threadIdx.y + j][threadIdx.x] = g_q[((size_t)b*TT + t0 + threadIdx.y + j)*DD + d0 + threadIdx.x];
    __syncthreads();
    #pragma unroll
    for (int j = 0; j < 32; j += 8)
        out[((size_t)b*DD + d0 + threadIdx.y + j)*TT + t0 + threadIdx.x] = tile[threadIdx.x][threadIdx.y + j];
}

// ---- codebook -> fragment-packed uint4 layout + halfnorms ----
__global__ void cb_split(const float* __restrict__ cbs) {
    int g = blockIdx.x * 128 + threadIdx.x;   // 0..8191 = s*1024 + j
    int s    = g >> 10;
    int j    = g & 1023;
    int blk  = j >> 3;
    int n_ib = j & 7;
    const float* src = cbs + (size_t)g * DD;
    float s2 = 0.0f;
    #pragma unroll
    for (int k = 0; k < DD; k++) {
        float v = src[k];
        s2 += v*v;
        __half h = __float2half_rn(v);
        int kstep = k >> 4, kk = k & 15;
        int kpair = kstep >> 1, kodd = kstep & 1;
        int reg  = kk >> 3;
        int lane = n_ib*4 + ((kk & 7) >> 1);
        int elem = kk & 1;
        size_t idx = ((((size_t)s*128 + blk)*2 + kpair)*32 + lane)*8 + kodd*4 + reg*2 + elem;
        g_cbfrag[idx] = h;
    }
    g_hn[g] = 0.5f * s2;
}

__global__ void zero_acc() {
    int i = blockIdx.x * 256 + threadIdx.x;
    if (i < SS*KK) g_cnt[i] = 0u;
    if (i < SS)    g_loss[i] = 0.0f;
}

// ---- fused all-stages kernel ----
extern __shared__ char smem_raw[];

#define LOADU(buf, blkbase, p) { \
    _Pragma("unroll") \
    for (int i_ = 0; i_ < 4; i_++) buf[i_] = __ldg(bf4 + (((blkbase) + i_)*2 + (p))*32); }

#define MMAU(base, buf, p) { \
    _Pragma("unroll") \
    for (int i_ = 0; i_ < 4; i_++) { \
        mma16816(acc[(base)+i_], ahf[2*(p)],   buf[i_].x, buf[i_].y); \
        mma16816(acc[(base)+i_], ahf[2*(p)+1], buf[i_].z, buf[i_].w); } }

__global__ __launch_bounds__(256, 2)
void rvq_all(const float* __restrict__ cbs) {
    const int tid  = threadIdx.x;
    const int w    = tid >> 5;
    const int lane = tid & 31;
    const int wrow = w >> 1;          // 0..3: rows wrow*16..+15
    const int wcol = w & 1;           // 0..1: blocks wcol*64..+63
    const int row0 = blockIdx.x * TM;
    uint32_t sb;
    asm("{ .reg .u64 t; cvta.to.shared.u64 t, %1; cvt.u32.u64 %0, t; }" : "=r"(sb) : "l"(smem_raw));

    float* hn_all = (float*)(smem_raw + SM_HN);
    int*   fin  = (int*)(smem_raw + SM_FIN);
    float* red  = (float*)(smem_raw + SM_RED);
    int*   top4 = (int*)(smem_raw + SM_TOP4);
    float* m4v  = (float*)(smem_raw + SM_M4V);
    int*   m4i  = (int*)(smem_raw + SM_M4I);
    float* Af   = (float*)(smem_raw + SM_AF);

    // ---- prologue: fp32 residual tile + ALL stages' halfnorms ----
    {
        const char* af = (const char*)(g_res + (size_t)row0*DD);
        #pragma unroll
        for (int g = 0; g < 4; g++) {
            int idx = g*256 + tid;              // 1024 granules
            int r = idx >> 4, c = idx & 15;
            cpa16(sb + SM_AF + r*(RSTRF*4) + c*16, af + r*256 + c*16);
        }
        #pragma unroll
        for (int g = 0; g < 8; g++) {
            int idx = g*256 + tid;              // 2048 granules
            cpa16(sb + SM_HN + idx*16, (const char*)g_hn + idx*16);
        }
        cpa_commit();
        cpa_wait0();
    }
    __syncthreads();

    const uint32_t a_addr = sb + SM_AH + (wrow*16 + (lane & 15))*RSTR + (lane >> 4)*16;
    const int r0 = wrow*16 + (lane >> 2);     // thread's first row
    const int slot = wcol*4 + (lane & 3);

    for (int stage = 0; stage < SS; stage++) {
        const float* hns = hn_all + stage*KK;
        const float* cb  = cbs + (size_t)stage*KK*DD;

        // build Ah (fp16) from Af
        {
            int r  = tid >> 2;
            int k0 = (tid & 3) * 16;
            const float* src = Af + r*RSTRF + k0;
            __half2* dst = (__half2*)(smem_raw + SM_AH + r*RSTR + k0*2);
            #pragma unroll
            for (int j = 0; j < 8; j++)
                dst[j] = __floats2half2_rn(src[j*2], src[j*2+1]);
        }
        __syncthreads();

        uint32_t ahf[4][4];
        #pragma unroll
        for (int s = 0; s < 4; s++) ldsm_x4(ahf[s], a_addr + s*32);

        const uint4* bf4 = ((const uint4*)g_cbfrag) + (size_t)stage*8192 + lane;

        float bv0_0 = -FLT_MAX, bv1_0 = -FLT_MAX, bv0_1 = -FLT_MAX, bv1_1 = -FLT_MAX;
        int   bi0_0 = 0x7fffffff, bi1_0 = 0x7fffffff, bi0_1 = 0x7fffffff, bi1_1 = 0x7fffffff;

        uint4 bufA[4], bufB[4];
        LOADU(bufA, wcol*64, 0);
        for (int cg = 0; cg < 8; cg++) {
            const int blk0  = wcol*64 + cg*8;
            const int cbase = blk0*8 + (lane & 3)*2;

            float acc[8][4];
            #pragma unroll
            for (int nb = 0; nb < 8; nb++) {
                float h0 = -hns[cbase + nb*8];
                float h1 = -hns[cbase + nb*8 + 1];
                acc[nb][0] = h0; acc[nb][1] = h1; acc[nb][2] = h0; acc[nb][3] = h1;
            }

            LOADU(bufB, blk0 + 4, 0);
            MMAU(0, bufA, 0);
            LOADU(bufA, blk0, 1);
            MMAU(4, bufB, 0);
            LOADU(bufB, blk0 + 4, 1);
            MMAU(0, bufA, 1);
            if (cg < 7) LOADU(bufA, blk0 + 8, 0);
            MMAU(4, bufB, 1);

            // branchless fmax tree per row, rare top-2 insert
            float x0 = fmaxf(fmaxf(acc[0][0], acc[0][1]), fmaxf(acc[1][0], acc[1][1]));
            float x1 = fmaxf(fmaxf(acc[2][0], acc[2][1]), fmaxf(acc[3][0], acc[3][1]));
            float x2 = fmaxf(fmaxf(acc[4][0], acc[4][1]), fmaxf(acc[5][0], acc[5][1]));
            float x3 = fmaxf(fmaxf(acc[6][0], acc[6][1]), fmaxf(acc[7][0], acc[7][1]));
            float m0 = fmaxf(fmaxf(x0, x1), fmaxf(x2, x3));
            float y0 = fmaxf(fmaxf(acc[0][2], acc[0][3]), fmaxf(acc[1][2], acc[1][3]));
            float y1 = fmaxf(fmaxf(acc[2][2], acc[2][3]), fmaxf(acc[3][2], acc[3][3]));
            float y2 = fmaxf(fmaxf(acc[4][2], acc[4][3]), fmaxf(acc[5][2], acc[5][3]));
            float y3 = fmaxf(fmaxf(acc[6][2], acc[6][3]), fmaxf(acc[7][2], acc[7][3]));
            float m1 = fmaxf(fmaxf(y0, y1), fmaxf(y2, y3));

            if (m0 > bv1_0) {
                #pragma unroll
                for (int nb = 0; nb < 8; nb++) {
                    int col = cbase + nb*8;
                    ins2(acc[nb][0], col,     bv0_0, bi0_0, bv1_0, bi1_0);
                    ins2(acc[nb][1], col + 1, bv0_0, bi0_0, bv1_0, bi1_0);
                }
            }
            if (m1 > bv1_1) {
                #pragma unroll
                for (int nb = 0; nb < 8; nb++) {
                    int col = cbase + nb*8;
                    ins2(acc[nb][2], col,     bv0_1, bi0_1, bv1_1, bi1_1);
                    ins2(acc[nb][3], col + 1, bv0_1, bi0_1, bv1_1, bi1_1);
                }
            }
        }

        // ---- write per-thread top-2 (16 entries per row) ----
        m4v[r0*16 + slot*2 + 0] = bv0_0;  m4i[r0*16 + slot*2 + 0] = bi0_0;
        m4v[r0*16 + slot*2 + 1] = bv1_0;  m4i[r0*16 + slot*2 + 1] = bi1_0;
        m4v[(r0+8)*16 + slot*2 + 0] = bv0_1;  m4i[(r0+8)*16 + slot*2 + 0] = bi0_1;
        m4v[(r0+8)*16 + slot*2 + 1] = bv1_1;  m4i[(r0+8)*16 + slot*2 + 1] = bi1_1;
        __syncthreads();

        // ---- merge: one thread per row, top-4 of 16 ----
        if (tid < TM) {
            float mv[4] = {-FLT_MAX, -FLT_MAX, -FLT_MAX, -FLT_MAX};
            int   mi[4] = {0x7fffffff, 0x7fffffff, 0x7fffffff, 0x7fffffff};
            #pragma unroll 4
            for (int e = 0; e < 16; e++) {
                float v = m4v[tid*16 + e];
                int   i = m4i[tid*16 + e];
                if (v > mv[3] || (v == mv[3] && i < mi[3])) {
                    int k = 3;
                    while (k > 0 && (v > mv[k-1] || (v == mv[k-1] && i < mi[k-1]))) {
                        mv[k] = mv[k-1]; mi[k] = mi[k-1]; k--;
                    }
                    mv[k] = v; mi[k] = i;
                }
            }
            #pragma unroll
            for (int k = 0; k < 4; k++) top4[tid*4 + k] = mi[k];
        }
        __syncthreads();

        // ---- exact fp32 rescore: 4 threads per row ----
        {
            int row = tid >> 2;
            int c   = tid & 3;
            int idx = top4[row*4 + c];
            const float4* cp = (const float4*)(cb + (size_t)idx*DD);
            const float*  af = Af + row*RSTRF;
            float s0 = 0.f, s1 = 0.f, s2 = 0.f, s3 = 0.f;
            #pragma unroll
            for (int u = 0; u < 16; u++) {
                float4 q = __ldg(cp + u);
                s0 += q.x * af[u*4];
                s1 += q.y * af[u*4+1];
                s2 += q.z * af[u*4+2];
                s3 += q.w * af[u*4+3];
            }
            float sc = (s0 + s1) + (s2 + s3) - hns[idx];
            #pragma unroll
            for (int off = 1; off <= 2; off <<= 1) {
                float ov = __shfl_xor_sync(0xffffffffu, sc, off);
                int   oi = __shfl_xor_sync(0xffffffffu, idx, off);
                if (ov > sc || (ov == sc && oi < idx)) { sc = ov; idx = oi; }
            }
            if (c == 0) {
                fin[row] = idx;
                atomicAdd(&g_cnt[stage*KK + idx], 1u);
            }
        }
        __syncthreads();

        // ---- update residual in smem: 4 threads per row, 16 d's each ----
        {
            const int row = tid >> 2;
            const int qt  = tid & 3;
            const int code = fin[row];
            const float4* qv = (const float4*)(cb + (size_t)code*DD + qt*16);
            float* af = Af + row*RSTRF + qt*16;
            float lsum = 0.0f;
            #pragma unroll
            for (int u = 0; u < 4; u++) {
                float4 q4 = __ldg(qv + u);
                float e0 = q4.x - af[u*4+0];
                float e1 = q4.y - af[u*4+1];
                float e2 = q4.z - af[u*4+2];
                float e3 = q4.w - af[u*4+3];
                lsum += e0*e0 + e1*e1 + e2*e2 + e3*e3;
                af[u*4+0] = -e0; af[u*4+1] = -e1; af[u*4+2] = -e2; af[u*4+3] = -e3;
            }
            #pragma unroll
            for (int o = 16; o > 0; o >>= 1) lsum += __shfl_down_sync(0xffffffffu, lsum, o);
            if (lane == 0) red[w] = lsum;
        }
        __syncthreads();
        if (tid == 0) {
            float tot = 0.0f;
            #pragma unroll
            for (int ww = 0; ww < 8; ww++) tot += red[ww];
            atomicAdd(&g_loss[stage], tot);
        }
        __syncthreads();
    }

    // ---- final: q_total = initial residual - final residual ----
    {
        const int row = tid >> 2;
        const int qt  = tid & 3;
        const float4* rip = (const float4*)(g_res + (size_t)(row0+row)*DD + qt*16);
        float4*       qp  = (float4*)(g_q   + (size_t)(row0+row)*DD + qt*16);
        const float*  af  = Af + row*RSTRF + qt*16;
        #pragma unroll
        for (int u = 0; u < 4; u++) {
            float4 ri = __ldg(rip + u);
            float4 q;
            q.x = ri.x - af[u*4+0];
            q.y = ri.y - af[u*4+1];
            q.z = ri.z - af[u*4+2];
            q.w = ri.w - af[u*4+3];
            qp[u] = q;
        }
    }
}

// ---- losses + perplexities ----
__global__ void finalize(float* __restrict__ out) {
    const int s = blockIdx.x;
    __shared__ float sh[256];
    float e = 0.0f;
    for (int k = threadIdx.x; k < KK; k += 256) {
        float p = (float)g_cnt[s*KK + k] / (float)NV;
        e += p * logf(p + 1e-10f);
    }
    sh[threadIdx.x] = e;
    __syncthreads();
    for (int o = 128; o > 0; o >>= 1) {
        if (threadIdx.x < o) sh[threadIdx.x] += sh[threadIdx.x + o];
        __syncthreads();
    }
    if (threadIdx.x == 0) {
        out[ZQ_ELEMS + s]      = g_loss[s] / (float)(NV*DD);
        out[ZQ_ELEMS + SS + s] = expf(-sh[0]);
    }
}

extern "C" void kernel_launch(void* const* d_in, const int* in_sizes, int n_in,
                              void* d_out, int out_size) {
    const float* z   = (const float*)d_in[0];
    const float* cbs = (const float*)d_in[1];
    float* out = (float*)d_out;

    static int inited = 0;
    if (!inited) {
        cudaFuncSetAttribute(rvq_all, cudaFuncAttributeMaxDynamicSharedMemorySize, SM_TOTAL);
        inited = 1;
    }

    dim3 tb(32, 8);
    transpose_in<<<dim3(TT/32, DD/32, NB), tb>>>(z);
    zero_acc<<<32, 256>>>();
    cb_split<<<(SS*KK)/128, 128>>>(cbs);
    rvq_all<<<NV/TM, 256, SM_TOTAL>>>(cbs);
    finalize<<<SS, 256>>>(out);
    transpose_out<<<dim3(TT/32, DD/32, NB), tb>>>(out);
}